// round 13
// baseline (speedup 1.0000x reference)
#include <cuda_runtime.h>
#include <cuda_bf16.h>
#include <math.h>
#include <stdint.h>

#define NUM      512
#define DH       64
#define EMAX     4096
#define MAIN_N   10
#define THREADS  1024
#define ZSTR     264           // z / h2 row stride bytes
#define ASTR     144           // A / B tile row stride bytes (36 words: conflict-free)

// ------------------------- device scratch (no allocs allowed) ----------------
__device__ __align__(16) int2 g_csr[EMAX];           // {r*ZSTR, coef bits}
__device__ __align__(4) unsigned short g_row[EMAX];  // plain r (layer 3)
__device__ int       g_ptr[NUM + 1];
__device__ float     g_EW1[NUM * DH];
__device__ uint32_t  g_BT2hi[DH * DH / 2];  // W2^T hi, [n][k] packed bf16x2
__device__ uint32_t  g_BT2lo[DH * DH / 2];  // W2^T lo

// ------------------------- mma / cp.async helpers ----------------------------
static __device__ __forceinline__ void ldm4(uint32_t* r, uint32_t addr){
    asm volatile("ldmatrix.sync.aligned.m8n8.x4.shared.b16 {%0,%1,%2,%3}, [%4];"
                 : "=r"(r[0]), "=r"(r[1]), "=r"(r[2]), "=r"(r[3]) : "r"(addr));
}
static __device__ __forceinline__ void mma_bf16(float& c0, float& c1, float& c2, float& c3,
                                                const uint32_t* a, uint32_t b0, uint32_t b1){
    asm volatile("mma.sync.aligned.m16n8k16.row.col.f32.bf16.bf16.f32 "
                 "{%0,%1,%2,%3}, {%4,%5,%6,%7}, {%8,%9}, {%0,%1,%2,%3};"
                 : "+f"(c0), "+f"(c1), "+f"(c2), "+f"(c3)
                 : "r"(a[0]), "r"(a[1]), "r"(a[2]), "r"(a[3]), "r"(b0), "r"(b1));
}
static __device__ __forceinline__ void cpa16(uint32_t dst, const void* src){
    asm volatile("cp.async.cg.shared.global [%0], [%1], 16;" :: "r"(dst), "l"(src));
}
static __device__ __forceinline__ void cpa4(uint32_t dst, const void* src){
    asm volatile("cp.async.ca.shared.global [%0], [%1], 4;" :: "r"(dst), "l"(src));
}

// ------------------------- unified prep: EW1 / W2-split / graph --------------
#define PS_CS    0
#define PS_RS    16384
#define PS_CNT   32768
#define PS_DEG   163840
#define PS_DINV  165888
#define PS_SPTR  167936
#define PS_TOTAL 170000

__global__ void __launch_bounds__(1024)
prep_all(const float* __restrict__ emb, const float* __restrict__ W1,
         const float* __restrict__ W2,
         const int* __restrict__ erow, const int* __restrict__ ecol, int E)
{
    const int blk = blockIdx.x;
    if (blk < 32){
        int i = blk * 1024 + threadIdx.x;            // n*64 + d
        int n = i >> 6, d = i & 63;
        float acc = 0.f;
#pragma unroll
        for (int k = 0; k < DH; k++) acc += emb[n * DH + k] * W1[k * DH + d];
        g_EW1[i] = acc;
        return;
    }
    if (blk == 32){
        for (int idx = threadIdx.x; idx < DH * DH / 2; idx += 1024){
            int o = idx >> 5, kp = idx & 31;         // n=o, k pair 2kp,2kp+1
            float w0 = W2[(2 * kp) * DH + o];
            float w1 = W2[(2 * kp + 1) * DH + o];
            __nv_bfloat162 hi = __float22bfloat162_rn(make_float2(w0, w1));
            float r0 = w0 - __bfloat162float(hi.x);
            float r1 = w1 - __bfloat162float(hi.y);
            __nv_bfloat162 lo = __float22bfloat162_rn(make_float2(r0, r1));
            g_BT2hi[idx] = *(uint32_t*)&hi;
            g_BT2lo[idx] = *(uint32_t*)&lo;
        }
        return;
    }

    // ---- graph -> stable col-sorted CSR -----------------------------------------
    extern __shared__ char psm[];
    int*            cs   = (int*)(psm + PS_CS);
    int*            rs   = (int*)(psm + PS_RS);
    unsigned short* cnt  = (unsigned short*)(psm + PS_CNT);
    int*            deg  = (int*)(psm + PS_DEG);
    float*          dinv = (float*)(psm + PS_DINV);
    int*            sptr = (int*)(psm + PS_SPTR);

    const int t  = threadIdx.x;
    const int wd = t >> 5;
    const int ln = t & 31;

    for (int e = t; e < EMAX; e += 1024){
        cs[e] = (e < E) ? ecol[e] : -1;
        rs[e] = (e < E) ? erow[e] : 0;
        g_csr[e] = make_int2(0, 0);                  // pads stay coef=0
        g_row[e] = 0;
    }
    for (int i = t; i < (128 * NUM) / 2; i += 1024)
        ((unsigned*)cnt)[i] = 0;
    __syncthreads();

    for (int ck = wd; ck < 128; ck += 32){
        int col = cs[ck * 32 + ln];
        unsigned mask = __match_any_sync(0xffffffffu, col);
        if (col >= 0 && ln == (__ffs(mask) - 1))
            cnt[ck * NUM + col] = (unsigned short)__popc(mask);
    }
    __syncthreads();

    if (t < NUM){
        int run = 0;
#pragma unroll 4
        for (int k = 0; k < 128; k++){
            int v = cnt[k * NUM + t];
            cnt[k * NUM + t] = (unsigned short)run;
            run += v;
        }
        deg[t]  = run;
        dinv[t] = run > 0 ? rsqrtf((float)run) : 0.f;
    }
    __syncthreads();
    if (t == 0){
        int s = 0;
        for (int n = 0; n < NUM; n++){ sptr[n] = s; s += deg[n]; }
        sptr[NUM] = s;
    }
    __syncthreads();

    for (int ck = wd; ck < 128; ck += 32){
        int e   = ck * 32 + ln;
        int col = cs[e];
        unsigned mask = __match_any_sync(0xffffffffu, col);
        int rank = __popc(mask & ((1u << ln) - 1u));
        if (col >= 0){
            int r   = rs[e];
            int pos = sptr[col] + (int)cnt[ck * NUM + col] + rank;
            g_csr[pos] = make_int2(r * ZSTR, __float_as_int(dinv[col] * dinv[r]));
            g_row[pos] = (unsigned short)r;
        }
    }
    if (t <= NUM) g_ptr[t] = sptr[t];
}

// ------------------------- fused GCN mega-kernel (one CTA per batch) ----------
// smem layout (bytes):
//   region0: z[512x264]=135168 -> A_hi[512x144]@0 + A_lo @73728 -> h2[512x264]
//   meta [4096] int2  @ 147456 (32768)   {r*ZSTR, coef}
//   sptr [513]  i32   @ 180224 ( 2052) +pad
//   t3   [512]  f32   @ 184328 ( 2048)
//   lg   [512]  f32   @ 186376 ( 2048)
//   B_hi [64x144]     @ 188432 ( 9216)
//   B_lo [64x144]     @ 197648 ( 9216)
//   row3 [4096] u16   @ 206864 ( 8192)
#define SM_A_HI  0
#define SM_A_LO  73728
#define SM_META  147456
#define SM_PTR   180224
#define SM_T3    184328
#define SM_LG    186376
#define SM_BHI   188432
#define SM_BLO   197648
#define SM_ROW3  206864
#define SM_TOTAL 215056

static __device__ __forceinline__ uint32_t smem_u32(const void* p){
    uint32_t a;
    asm("{ .reg .u64 t; cvta.to.shared.u64 t, %1; cvt.u32.u64 %0, t; }"
        : "=r"(a) : "l"(p));
    return a;
}

__global__ void __launch_bounds__(THREADS, 1)
gcn_mega(const float* __restrict__ x,
         const float* __restrict__ b1,
         const float* __restrict__ b2,
         const float* __restrict__ W3,
         const float* __restrict__ b3,
         float* __restrict__ out)
{
    extern __shared__ char smraw[];
    int2*           meta = (int2*)(smraw + SM_META);
    int*            sptr = (int*)(smraw + SM_PTR);
    float*          t3   = (float*)(smraw + SM_T3);
    float*          lg   = (float*)(smraw + SM_LG);
    unsigned short* row3 = (unsigned short*)(smraw + SM_ROW3);

    const uint32_t sbase = smem_u32(smraw);
    const int t  = threadIdx.x;
    const int b  = blockIdx.x;
    const int ln = t & 31;               // lane
    const int gw = t >> 5;               // warp id 0..31
    const int loff = 8 * ln;             // this lane's dim-pair byte offset

    // ---- async-stage meta + row3 + B tiles; z-build overlapped -------------------
    {
#pragma unroll
        for (int i = t; i < EMAX / 2; i += THREADS)           // 16B chunks
            cpa16(sbase + SM_META + 16 * i, (const char*)g_csr + 16 * i);
#pragma unroll
        for (int i = t; i < EMAX / 8; i += THREADS)           // row3 16B chunks
            cpa16(sbase + SM_ROW3 + 16 * i, (const char*)g_row + 16 * i);
#pragma unroll
        for (int i = t; i < DH * DH / 2; i += THREADS){
            int n = i >> 5, kp = i & 31;
            cpa4(sbase + SM_BHI + n * ASTR + 4 * kp, &g_BT2hi[i]);
            cpa4(sbase + SM_BLO + n * ASTR + 4 * kp, &g_BT2lo[i]);
        }
        asm volatile("cp.async.commit_group;");
        if (t <= NUM) sptr[t] = g_ptr[t];

        // z = diag(x) * EW1 (x is a per-warp broadcast LDG; no xs staging)
        const float2* ew2 = (const float2*)g_EW1;
#pragma unroll
        for (int k = 0; k < (NUM * 32) / THREADS; k++){
            int i = t + k * THREADS;            // n*32 + jp
            int n = i >> 5, jp = i & 31;
            float xv = __ldg(x + b * NUM + n);  // all lanes same n -> broadcast
            float2 w = ew2[i];
            *(float2*)(smraw + n * ZSTR + 8 * jp) = make_float2(xv * w.x, xv * w.y);
        }
        asm volatile("cp.async.wait_group 0;");
    }
    __syncthreads();

    // ---- layer 1 agg into registers: warp gw owns nodes gw+32m ------------------
    float2 h1[16];
    {
        float b1x = b1[2 * ln], b1y = b1[2 * ln + 1];
#pragma unroll
        for (int m = 0; m < 16; m++){
            int n = gw + 32 * m;
            int e0 = sptr[n], e1 = sptr[n + 1];
            float a0 = 0.f, a1 = 0.f;
#pragma unroll 4
            for (int e = e0; e < e1; e++){
                int2  rc = meta[e];                        // LDS.64 broadcast
                float c  = __int_as_float(rc.y);
                float2 zv = *(const float2*)(smraw + rc.x + loff);
                a0 += c * zv.x;
                a1 += c * zv.y;
            }
            h1[m] = make_float2(fmaxf(a0 + b1x, 0.f), fmaxf(a1 + b1y, 0.f));
        }
    }
    __syncthreads();                      // all z reads complete (z dead)

    // ---- write h1 as bf16 hi/lo A tiles (overwrites z; 144B stride) -------------
#pragma unroll
    for (int m = 0; m < 16; m++){
        int n = gw + 32 * m;
        float2 v = h1[m];
        __nv_bfloat162 hi2 = __float22bfloat162_rn(v);
        float2 r = make_float2(v.x - __bfloat162float(hi2.x),
                               v.y - __bfloat162float(hi2.y));
        __nv_bfloat162 lo2 = __float22bfloat162_rn(r);
        *(__nv_bfloat162*)(smraw + SM_A_HI + n * ASTR + 4 * ln) = hi2;
        *(__nv_bfloat162*)(smraw + SM_A_LO + n * ASTR + 4 * ln) = lo2;
    }
    __syncthreads();

    // ---- load A fragments (warp w: rows 16w..16w+15, k 0..63, hi+lo) ------------
    uint32_t ah[16], al[16];
    {
        uint32_t abase = sbase + (16 * gw + (ln & 15)) * ASTR + ((ln >> 4) << 4);
#pragma unroll
        for (int kt = 0; kt < 4; kt++) ldm4(&ah[4 * kt], abase + SM_A_HI + 32 * kt);
#pragma unroll
        for (int kt = 0; kt < 4; kt++) ldm4(&al[4 * kt], abase + SM_A_LO + 32 * kt);
    }
    __syncthreads();                      // all A reads done; region reusable as h2

    // ---- h2 = h1 @ W2: 8 n-tiles x 4 k-tiles x 3 passes of mma.m16n8k16 ---------
    {
        const int rowa = 16 * gw + (ln >> 2);
#pragma unroll 1
        for (int nt = 0; nt < 8; nt++){
            float c0 = 0.f, c1 = 0.f, c2 = 0.f, c3 = 0.f;
            uint32_t boff = (uint32_t)((8 * nt + (ln >> 2)) * ASTR + 4 * (ln & 3));
#pragma unroll
            for (int kt = 0; kt < 4; kt++){
                uint32_t b0h = *(const uint32_t*)(smraw + SM_BHI + boff + 32 * kt);
                uint32_t b1h = *(const uint32_t*)(smraw + SM_BHI + boff + 32 * kt + 16);
                uint32_t b0l = *(const uint32_t*)(smraw + SM_BLO + boff + 32 * kt);
                uint32_t b1l = *(const uint32_t*)(smraw + SM_BLO + boff + 32 * kt + 16);
                mma_bf16(c0, c1, c2, c3, &ah[4 * kt], b0h, b1h);
                mma_bf16(c0, c1, c2, c3, &ah[4 * kt], b0l, b1l);
                mma_bf16(c0, c1, c2, c3, &al[4 * kt], b0h, b1h);
            }
            *(float2*)(smraw + rowa * ZSTR + 32 * nt + 8 * (ln & 3)) = make_float2(c0, c1);
            *(float2*)(smraw + (rowa + 8) * ZSTR + 32 * nt + 8 * (ln & 3)) = make_float2(c2, c3);
        }
    }
    __syncthreads();

    // ---- layer 2 agg + relu + W3 dot (dynamic node loop — R8 form) --------------
    {
        float b2x = b2[2 * ln], b2y = b2[2 * ln + 1];
        float w3x = W3[2 * ln], w3y = W3[2 * ln + 1];
        for (int n = gw; n < NUM; n += 32){
            int e0 = sptr[n], e1 = sptr[n + 1];
            float a0 = 0.f, a1 = 0.f;
#pragma unroll 4
            for (int e = e0; e < e1; e++){
                int2  rc = meta[e];
                float c  = __int_as_float(rc.y);
                float2 hv = *(const float2*)(smraw + rc.x + loff);
                a0 += c * hv.x;
                a1 += c * hv.y;
            }
            a0 = fmaxf(a0 + b2x, 0.f);
            a1 = fmaxf(a1 + b2y, 0.f);
            float v = a0 * w3x + a1 * w3y;
#pragma unroll
            for (int o = 16; o > 0; o >>= 1) v += __shfl_xor_sync(0xffffffffu, v, o);
            if (ln == 0) t3[n] = v;
        }
    }
    __syncthreads();

    // ---- layer 3 aggregation: logits ----------------------------------------------
    if (t < NUM){
        float a = b3[0];
        int e0 = sptr[t], e1 = sptr[t + 1];
#pragma unroll 4
        for (int e = e0; e < e1; e++)
            a += __int_as_float(meta[e].y) * t3[row3[e]];
        lg[t] = a;
    }
    __syncthreads();

    // ---- softmax over [0,10), sigmoid elsewhere ------------------------------------
    if (t < NUM){
        float v = lg[t];
        if (t < 32){
            float xv = (t < MAIN_N) ? v : -INFINITY;
            float m = xv;
#pragma unroll
            for (int o = 16; o > 0; o >>= 1) m = fmaxf(m, __shfl_xor_sync(0xffffffffu, m, o));
            float p = (t < MAIN_N) ? expf(xv - m) : 0.f;
            float s = p;
#pragma unroll
            for (int o = 16; o > 0; o >>= 1) s += __shfl_xor_sync(0xffffffffu, s, o);
            if (t < MAIN_N) out[b * NUM + t] = p / s;
        }
        if (t >= MAIN_N) out[b * NUM + t] = 1.f / (1.f + expf(-v));
    }
}

// ------------------------- launcher ------------------------------------------
extern "C" void kernel_launch(void* const* d_in, const int* in_sizes, int n_in,
                              void* d_out, int out_size)
{
    const float* x    = (const float*)d_in[0];
    const float* emb  = (const float*)d_in[1];
    const float* W1   = (const float*)d_in[2];
    const float* b1   = (const float*)d_in[3];
    const float* W2   = (const float*)d_in[4];
    const float* b2   = (const float*)d_in[5];
    const float* W3   = (const float*)d_in[6];
    const float* b3   = (const float*)d_in[7];
    const int*  erow  = (const int*)d_in[8];
    const int*  ecol  = (const int*)d_in[9];
    float* out = (float*)d_out;

    const int E = in_sizes[8];
    const int B = in_sizes[0] / NUM;

    cudaFuncSetAttribute(gcn_mega, cudaFuncAttributeMaxDynamicSharedMemorySize, SM_TOTAL);
    cudaFuncSetAttribute(prep_all, cudaFuncAttributeMaxDynamicSharedMemorySize, PS_TOTAL);

    prep_all<<<34, 1024, PS_TOTAL>>>(emb, W1, W2, erow, ecol, E);
    gcn_mega<<<B, THREADS, SM_TOTAL>>>(x, b1, b2, W3, b3, out);

    (void)n_in; (void)out_size;
}

// round 14
// speedup vs baseline: 1.0398x; 1.0398x over previous
#include <cuda_runtime.h>
#include <cuda_bf16.h>
#include <math.h>
#include <stdint.h>

#define NUM      512
#define DH       64
#define EMAX     4096
#define MAIN_N   10
#define THREADS  1024
#define ZSTR     264           // z / h2 row stride bytes
#define ASTR     144           // A tile row stride bytes (36 words: conflict-free)
#define BSTR     320           // packed B row stride bytes (80 words: LDS.128 conflict-free)

// ------------------------- device scratch (no allocs allowed) ----------------
__device__ __align__(16) int2 g_csr[EMAX];  // {row, coef bits} col-sorted, stable
__device__ int       g_ptr[NUM + 1];
__device__ float     g_EW1[NUM * DH];
__device__ __align__(16) unsigned char g_Bpack[DH * BSTR];  // W2^T hi/lo interleaved

// ------------------------- mma / cp.async helpers ----------------------------
static __device__ __forceinline__ void ldm4(uint32_t* r, uint32_t addr){
    asm volatile("ldmatrix.sync.aligned.m8n8.x4.shared.b16 {%0,%1,%2,%3}, [%4];"
                 : "=r"(r[0]), "=r"(r[1]), "=r"(r[2]), "=r"(r[3]) : "r"(addr));
}
static __device__ __forceinline__ void mma_bf16(float& c0, float& c1, float& c2, float& c3,
                                                const uint32_t* a, uint32_t b0, uint32_t b1){
    asm volatile("mma.sync.aligned.m16n8k16.row.col.f32.bf16.bf16.f32 "
                 "{%0,%1,%2,%3}, {%4,%5,%6,%7}, {%8,%9}, {%0,%1,%2,%3};"
                 : "+f"(c0), "+f"(c1), "+f"(c2), "+f"(c3)
                 : "r"(a[0]), "r"(a[1]), "r"(a[2]), "r"(a[3]), "r"(b0), "r"(b1));
}
static __device__ __forceinline__ void cpa16(uint32_t dst, const void* src){
    asm volatile("cp.async.cg.shared.global [%0], [%1], 16;" :: "r"(dst), "l"(src));
}

// ------------------------- unified prep: EW1 / W2-pack / graph ---------------
#define PS_CS    0
#define PS_RS    16384
#define PS_CNT   32768
#define PS_DEG   163840
#define PS_DINV  165888
#define PS_SPTR  167936
#define PS_TOTAL 170000

__global__ void __launch_bounds__(1024)
prep_all(const float* __restrict__ emb, const float* __restrict__ W1,
         const float* __restrict__ W2,
         const int* __restrict__ erow, const int* __restrict__ ecol, int E)
{
    const int blk = blockIdx.x;
    if (blk < 32){
        int i = blk * 1024 + threadIdx.x;            // n*64 + d
        int n = i >> 6, d = i & 63;
        float acc = 0.f;
#pragma unroll
        for (int k = 0; k < DH; k++) acc += emb[n * DH + k] * W1[k * DH + d];
        g_EW1[i] = acc;
        return;
    }
    if (blk == 32){
        // interleaved pack: row n (output col), group g = kt*4+q holds
        // {hi(kp0), hi(kp0+4), lo(kp0), lo(kp0+4)} for k-pair kp0 = 8kt+q
        for (int idx = threadIdx.x; idx < DH * 16; idx += 1024){
            int n = idx >> 4, g = idx & 15;
            int kt = g >> 2, q = g & 3;
            int kp0 = 8 * kt + q, kp1 = kp0 + 4;
            float w00 = W2[(2 * kp0) * DH + n], w01 = W2[(2 * kp0 + 1) * DH + n];
            float w10 = W2[(2 * kp1) * DH + n], w11 = W2[(2 * kp1 + 1) * DH + n];
            __nv_bfloat162 h0 = __float22bfloat162_rn(make_float2(w00, w01));
            __nv_bfloat162 h1 = __float22bfloat162_rn(make_float2(w10, w11));
            __nv_bfloat162 l0 = __float22bfloat162_rn(
                make_float2(w00 - __bfloat162float(h0.x), w01 - __bfloat162float(h0.y)));
            __nv_bfloat162 l1 = __float22bfloat162_rn(
                make_float2(w10 - __bfloat162float(h1.x), w11 - __bfloat162float(h1.y)));
            uint4 v;
            v.x = *(uint32_t*)&h0; v.y = *(uint32_t*)&h1;
            v.z = *(uint32_t*)&l0; v.w = *(uint32_t*)&l1;
            *(uint4*)(g_Bpack + n * BSTR + g * 16) = v;
        }
        return;
    }

    // ---- graph -> stable col-sorted CSR -----------------------------------------
    extern __shared__ char psm[];
    int*            cs   = (int*)(psm + PS_CS);
    int*            rs   = (int*)(psm + PS_RS);
    unsigned short* cnt  = (unsigned short*)(psm + PS_CNT);
    int*            deg  = (int*)(psm + PS_DEG);
    float*          dinv = (float*)(psm + PS_DINV);
    int*            sptr = (int*)(psm + PS_SPTR);

    const int t  = threadIdx.x;
    const int wd = t >> 5;
    const int ln = t & 31;

    for (int e = t; e < EMAX; e += 1024){
        cs[e] = (e < E) ? ecol[e] : -1;
        rs[e] = (e < E) ? erow[e] : 0;
        g_csr[e] = make_int2(0, 0);                  // pads stay coef=0
    }
    for (int i = t; i < (128 * NUM) / 2; i += 1024)
        ((unsigned*)cnt)[i] = 0;
    __syncthreads();

    for (int ck = wd; ck < 128; ck += 32){
        int col = cs[ck * 32 + ln];
        unsigned mask = __match_any_sync(0xffffffffu, col);
        if (col >= 0 && ln == (__ffs(mask) - 1))
            cnt[ck * NUM + col] = (unsigned short)__popc(mask);
    }
    __syncthreads();

    if (t < NUM){
        int run = 0;
#pragma unroll 4
        for (int k = 0; k < 128; k++){
            int v = cnt[k * NUM + t];
            cnt[k * NUM + t] = (unsigned short)run;
            run += v;
        }
        deg[t]  = run;
        dinv[t] = run > 0 ? rsqrtf((float)run) : 0.f;
    }
    __syncthreads();
    if (t == 0){
        int s = 0;
        for (int n = 0; n < NUM; n++){ sptr[n] = s; s += deg[n]; }
        sptr[NUM] = s;
    }
    __syncthreads();

    for (int ck = wd; ck < 128; ck += 32){
        int e   = ck * 32 + ln;
        int col = cs[e];
        unsigned mask = __match_any_sync(0xffffffffu, col);
        int rank = __popc(mask & ((1u << ln) - 1u));
        if (col >= 0){
            int r   = rs[e];
            int pos = sptr[col] + (int)cnt[ck * NUM + col] + rank;
            g_csr[pos] = make_int2(r, __float_as_int(dinv[col] * dinv[r]));
        }
    }
    if (t <= NUM) g_ptr[t] = sptr[t];
}

// ------------------------- fused GCN mega-kernel (one CTA per batch) ----------
// smem layout (bytes):
//   region0: z[512x264]=135168 -> A_hi[512x144]@0 + A_lo @73728 -> h2[512x264]
//   meta [4096] int2  @ 147456 (32768)   {r, coef}
//   sptr [513]  i32   @ 180224 ( 2052)
//   t3   [512]  f32   @ 184328 ( 2048)
//   Bpack[64x320]     @ 186384 (20480)
#define SM_A_HI  0
#define SM_A_LO  73728
#define SM_META  147456
#define SM_PTR   180224
#define SM_T3    184328
#define SM_BP    186384
#define SM_TOTAL 206864

static __device__ __forceinline__ uint32_t smem_u32(const void* p){
    uint32_t a;
    asm("{ .reg .u64 t; cvta.to.shared.u64 t, %1; cvt.u32.u64 %0, t; }"
        : "=r"(a) : "l"(p));
    return a;
}

__global__ void __launch_bounds__(THREADS, 1)
gcn_mega(const float* __restrict__ x,
         const float* __restrict__ b1,
         const float* __restrict__ b2,
         const float* __restrict__ W3,
         const float* __restrict__ b3,
         float* __restrict__ out)
{
    extern __shared__ char smraw[];
    int2*  meta = (int2*)(smraw + SM_META);
    int*   sptr = (int*)(smraw + SM_PTR);
    float* t3   = (float*)(smraw + SM_T3);

    const uint32_t sbase = smem_u32(smraw);
    const int t  = threadIdx.x;
    const int b  = blockIdx.x;
    const int ln = t & 31;               // lane
    const int gw = t >> 5;               // warp id 0..31

    // ---- async-stage meta + packed B; z-build overlapped -------------------------
    {
#pragma unroll
        for (int i = t; i < EMAX / 2; i += THREADS)           // meta 16B chunks
            cpa16(sbase + SM_META + 16 * i, (const char*)g_csr + 16 * i);
#pragma unroll
        for (int i = t; i < (DH * BSTR) / 16; i += THREADS)   // Bpack 16B chunks
            cpa16(sbase + SM_BP + 16 * i, g_Bpack + 16 * i);
        asm volatile("cp.async.commit_group;");
        if (t <= NUM) sptr[t] = g_ptr[t];

        // z = diag(x) * EW1 (x is a per-warp broadcast LDG; no xs staging)
        const float2* ew2 = (const float2*)g_EW1;
#pragma unroll
        for (int k = 0; k < (NUM * 32) / THREADS; k++){
            int i = t + k * THREADS;            // n*32 + jp
            int n = i >> 5, jp = i & 31;
            float xv = __ldg(x + b * NUM + n);  // all lanes same n -> broadcast
            float2 w = ew2[i];
            *(float2*)(smraw + n * ZSTR + 8 * jp) = make_float2(xv * w.x, xv * w.y);
        }
        asm volatile("cp.async.wait_group 0;");
    }
    __syncthreads();

    // ---- layer 1 agg into registers: warp gw owns nodes gw+32m ------------------
    float2 h1[16];
    {
        float b1x = b1[2 * ln], b1y = b1[2 * ln + 1];
#pragma unroll
        for (int m = 0; m < 16; m++){
            int n = gw + 32 * m;
            int e0 = sptr[n], e1 = sptr[n + 1];
            float a0 = 0.f, a1 = 0.f;
#pragma unroll 4
            for (int e = e0; e < e1; e++){
                int2  rc = meta[e];                        // LDS.64 broadcast
                float c  = __int_as_float(rc.y);
                float2 zv = *(const float2*)(smraw + rc.x * ZSTR + 8 * ln);
                a0 += c * zv.x;
                a1 += c * zv.y;
            }
            h1[m] = make_float2(fmaxf(a0 + b1x, 0.f), fmaxf(a1 + b1y, 0.f));
        }
    }
    __syncthreads();                      // all z reads complete (z dead)

    // ---- write h1 as bf16 hi/lo A tiles (overwrites z; 144B stride) -------------
#pragma unroll
    for (int m = 0; m < 16; m++){
        int n = gw + 32 * m;
        float2 v = h1[m];
        __nv_bfloat162 hi2 = __float22bfloat162_rn(v);
        float2 r = make_float2(v.x - __bfloat162float(hi2.x),
                               v.y - __bfloat162float(hi2.y));
        __nv_bfloat162 lo2 = __float22bfloat162_rn(r);
        *(__nv_bfloat162*)(smraw + SM_A_HI + n * ASTR + 4 * ln) = hi2;
        *(__nv_bfloat162*)(smraw + SM_A_LO + n * ASTR + 4 * ln) = lo2;
    }
    __syncthreads();

    // ---- load A fragments (warp w: rows 16w..16w+15, k 0..63, hi+lo) ------------
    uint32_t ah[16], al[16];
    {
        uint32_t abase = sbase + (16 * gw + (ln & 15)) * ASTR + ((ln >> 4) << 4);
#pragma unroll
        for (int kt = 0; kt < 4; kt++) ldm4(&ah[4 * kt], abase + SM_A_HI + 32 * kt);
#pragma unroll
        for (int kt = 0; kt < 4; kt++) ldm4(&al[4 * kt], abase + SM_A_LO + 32 * kt);
    }
    __syncthreads();                      // all A reads done; region reusable as h2

    // ---- h2 = h1 @ W2: 8 n-tiles x 4 k-tiles x 3 passes of mma.m16n8k16 ---------
    {
        const int rowa = 16 * gw + (ln >> 2);
#pragma unroll 1
        for (int nt = 0; nt < 8; nt++){
            float c0 = 0.f, c1 = 0.f, c2 = 0.f, c3 = 0.f;
            const char* bp = smraw + SM_BP + (8 * nt + (ln >> 2)) * BSTR + (ln & 3) * 16;
#pragma unroll
            for (int kt = 0; kt < 4; kt++){
                uint4 v = *(const uint4*)(bp + kt * 64);   // {b0h,b1h,b0l,b1l}
                mma_bf16(c0, c1, c2, c3, &ah[4 * kt], v.x, v.y);
                mma_bf16(c0, c1, c2, c3, &ah[4 * kt], v.z, v.w);
                mma_bf16(c0, c1, c2, c3, &al[4 * kt], v.x, v.y);
            }
            *(float2*)(smraw + rowa * ZSTR + 32 * nt + 8 * (ln & 3)) = make_float2(c0, c1);
            *(float2*)(smraw + (rowa + 8) * ZSTR + 32 * nt + 8 * (ln & 3)) = make_float2(c2, c3);
        }
    }
    __syncthreads();

    // ---- layer 2 agg + relu + W3 dot (dynamic node loop — R8 form) --------------
    {
        float b2x = b2[2 * ln], b2y = b2[2 * ln + 1];
        float w3x = W3[2 * ln], w3y = W3[2 * ln + 1];
        for (int n = gw; n < NUM; n += 32){
            int e0 = sptr[n], e1 = sptr[n + 1];
            float a0 = 0.f, a1 = 0.f;
#pragma unroll 4
            for (int e = e0; e < e1; e++){
                int2  rc = meta[e];
                float c  = __int_as_float(rc.y);
                float2 hv = *(const float2*)(smraw + rc.x * ZSTR + 8 * ln);
                a0 += c * hv.x;
                a1 += c * hv.y;
            }
            a0 = fmaxf(a0 + b2x, 0.f);
            a1 = fmaxf(a1 + b2y, 0.f);
            float v = a0 * w3x + a1 * w3y;
#pragma unroll
            for (int o = 16; o > 0; o >>= 1) v += __shfl_xor_sync(0xffffffffu, v, o);
            if (ln == 0) t3[n] = v;
        }
    }
    __syncthreads();

    // ---- layer 3 logits (register-resident) + softmax/sigmoid --------------------
    if (t < NUM){
        float a = b3[0];
        int e0 = sptr[t], e1 = sptr[t + 1];
#pragma unroll 4
        for (int e = e0; e < e1; e++){
            int2 rc = meta[e];
            a += __int_as_float(rc.y) * t3[rc.x];
        }
        if (t < 32){
            float xv = (t < MAIN_N) ? a : -INFINITY;
            float m = xv;
#pragma unroll
            for (int o = 16; o > 0; o >>= 1) m = fmaxf(m, __shfl_xor_sync(0xffffffffu, m, o));
            float p = (t < MAIN_N) ? expf(xv - m) : 0.f;
            float s = p;
#pragma unroll
            for (int o = 16; o > 0; o >>= 1) s += __shfl_xor_sync(0xffffffffu, s, o);
            if (t < MAIN_N) out[b * NUM + t] = p / s;
        }
        if (t >= MAIN_N) out[b * NUM + t] = 1.f / (1.f + expf(-a));
    }
}

// ------------------------- launcher ------------------------------------------
extern "C" void kernel_launch(void* const* d_in, const int* in_sizes, int n_in,
                              void* d_out, int out_size)
{
    const float* x    = (const float*)d_in[0];
    const float* emb  = (const float*)d_in[1];
    const float* W1   = (const float*)d_in[2];
    const float* b1   = (const float*)d_in[3];
    const float* W2   = (const float*)d_in[4];
    const float* b2   = (const float*)d_in[5];
    const float* W3   = (const float*)d_in[6];
    const float* b3   = (const float*)d_in[7];
    const int*  erow  = (const int*)d_in[8];
    const int*  ecol  = (const int*)d_in[9];
    float* out = (float*)d_out;

    const int E = in_sizes[8];
    const int B = in_sizes[0] / NUM;

    cudaFuncSetAttribute(gcn_mega, cudaFuncAttributeMaxDynamicSharedMemorySize, SM_TOTAL);
    cudaFuncSetAttribute(prep_all, cudaFuncAttributeMaxDynamicSharedMemorySize, PS_TOTAL);

    prep_all<<<34, 1024, PS_TOTAL>>>(emb, W1, W2, erow, ecol, E);
    gcn_mega<<<B, THREADS, SM_TOTAL>>>(x, b1, b2, W3, b3, out);

    (void)n_in; (void)out_size;
}

// round 15
// speedup vs baseline: 1.0513x; 1.0111x over previous
#include <cuda_runtime.h>
#include <cuda_bf16.h>
#include <math.h>
#include <stdint.h>

#define NUM      512
#define DH       64
#define EMAX     4096
#define MAIN_N   10
#define THREADS  1024
#define ZSTR     264           // z / h2 row stride bytes
#define ASTR     144           // A tile row stride bytes (36 words: conflict-free)
#define BSTR     320           // packed B row stride bytes (80 words: LDS.128 conflict-free)

// ------------------------- device scratch (no allocs allowed) ----------------
__device__ __align__(16) int2 g_csr[EMAX];  // {row, coef bits} col-sorted, stable
__device__ int       g_ptr[NUM + 1];
__device__ float     g_EW1[NUM * DH];
__device__ __align__(16) unsigned char g_Bpack[DH * BSTR];  // W2^T hi/lo interleaved

// ------------------------- mma / cp.async helpers ----------------------------
static __device__ __forceinline__ void ldm4(uint32_t* r, uint32_t addr){
    asm volatile("ldmatrix.sync.aligned.m8n8.x4.shared.b16 {%0,%1,%2,%3}, [%4];"
                 : "=r"(r[0]), "=r"(r[1]), "=r"(r[2]), "=r"(r[3]) : "r"(addr));
}
static __device__ __forceinline__ void mma_bf16(float& c0, float& c1, float& c2, float& c3,
                                                const uint32_t* a, uint32_t b0, uint32_t b1){
    asm volatile("mma.sync.aligned.m16n8k16.row.col.f32.bf16.bf16.f32 "
                 "{%0,%1,%2,%3}, {%4,%5,%6,%7}, {%8,%9}, {%0,%1,%2,%3};"
                 : "+f"(c0), "+f"(c1), "+f"(c2), "+f"(c3)
                 : "r"(a[0]), "r"(a[1]), "r"(a[2]), "r"(a[3]), "r"(b0), "r"(b1));
}
static __device__ __forceinline__ void cpa16(uint32_t dst, const void* src){
    asm volatile("cp.async.cg.shared.global [%0], [%1], 16;" :: "r"(dst), "l"(src));
}

// ------------------------- unified prep: EW1 / W2-pack / graph ---------------
#define PS_CS    0
#define PS_RS    16384
#define PS_CNT   32768
#define PS_DEG   163840
#define PS_DINV  165888
#define PS_SPTR  167936
#define PS_WP    169992
#define PS_TOTAL 170128

__global__ void __launch_bounds__(1024)
prep_all(const float* __restrict__ emb, const float* __restrict__ W1,
         const float* __restrict__ W2,
         const int* __restrict__ erow, const int* __restrict__ ecol, int E)
{
    const int blk = blockIdx.x;
    if (blk < 32){
        int i = blk * 1024 + threadIdx.x;            // n*64 + d
        int n = i >> 6, d = i & 63;
        float acc = 0.f;
#pragma unroll
        for (int k = 0; k < DH; k++) acc += emb[n * DH + k] * W1[k * DH + d];
        g_EW1[i] = acc;
        return;
    }
    if (blk == 32){
        // interleaved pack: row n (output col), group g = kt*4+q holds
        // {hi(kp0), hi(kp0+4), lo(kp0), lo(kp0+4)} for k-pair kp0 = 8kt+q
        for (int idx = threadIdx.x; idx < DH * 16; idx += 1024){
            int n = idx >> 4, g = idx & 15;
            int kt = g >> 2, q = g & 3;
            int kp0 = 8 * kt + q, kp1 = kp0 + 4;
            float w00 = W2[(2 * kp0) * DH + n], w01 = W2[(2 * kp0 + 1) * DH + n];
            float w10 = W2[(2 * kp1) * DH + n], w11 = W2[(2 * kp1 + 1) * DH + n];
            __nv_bfloat162 h0 = __float22bfloat162_rn(make_float2(w00, w01));
            __nv_bfloat162 h1 = __float22bfloat162_rn(make_float2(w10, w11));
            __nv_bfloat162 l0 = __float22bfloat162_rn(
                make_float2(w00 - __bfloat162float(h0.x), w01 - __bfloat162float(h0.y)));
            __nv_bfloat162 l1 = __float22bfloat162_rn(
                make_float2(w10 - __bfloat162float(h1.x), w11 - __bfloat162float(h1.y)));
            uint4 v;
            v.x = *(uint32_t*)&h0; v.y = *(uint32_t*)&h1;
            v.z = *(uint32_t*)&l0; v.w = *(uint32_t*)&l1;
            *(uint4*)(g_Bpack + n * BSTR + g * 16) = v;
        }
        return;
    }

    // ---- graph -> stable col-sorted CSR -----------------------------------------
    extern __shared__ char psm[];
    int*            cs   = (int*)(psm + PS_CS);
    int*            rs   = (int*)(psm + PS_RS);
    unsigned short* cnt  = (unsigned short*)(psm + PS_CNT);
    int*            deg  = (int*)(psm + PS_DEG);
    float*          dinv = (float*)(psm + PS_DINV);
    int*            sptr = (int*)(psm + PS_SPTR);
    int*            wpart= (int*)(psm + PS_WP);

    const int t  = threadIdx.x;
    const int wd = t >> 5;
    const int ln = t & 31;

    for (int e = t; e < EMAX; e += 1024){
        cs[e] = (e < E) ? ecol[e] : -1;
        rs[e] = (e < E) ? erow[e] : 0;
        g_csr[e] = make_int2(0, 0);                  // pads stay coef=0
    }
    for (int i = t; i < (128 * NUM) / 2; i += 1024)
        ((unsigned*)cnt)[i] = 0;
    __syncthreads();

    for (int ck = wd; ck < 128; ck += 32){
        int col = cs[ck * 32 + ln];
        unsigned mask = __match_any_sync(0xffffffffu, col);
        if (col >= 0 && ln == (__ffs(mask) - 1))
            cnt[ck * NUM + col] = (unsigned short)__popc(mask);
    }
    __syncthreads();

    if (t < NUM){
        int run = 0;
#pragma unroll 4
        for (int k = 0; k < 128; k++){
            int v = cnt[k * NUM + t];
            cnt[k * NUM + t] = (unsigned short)run;
            run += v;
        }
        deg[t]  = run;
        dinv[t] = run > 0 ? rsqrtf((float)run) : 0.f;
    }
    __syncthreads();

    // ---- parallel exclusive scan: sptr[t] = sum of deg[0..t) ----------------------
    {
        int v = (t < NUM) ? deg[t] : 0;
        int inc = v;
#pragma unroll
        for (int o = 1; o < 32; o <<= 1){
            int u = __shfl_up_sync(0xffffffffu, inc, o);
            if (ln >= o) inc += u;
        }
        if (ln == 31) wpart[wd] = inc;               // inclusive warp total (wd 0..31)
        __syncthreads();
        if (wd == 0){
            int p = wpart[ln];
            int ip = p;
#pragma unroll
            for (int o = 1; o < 32; o <<= 1){
                int u = __shfl_up_sync(0xffffffffu, ip, o);
                if (ln >= o) ip += u;
            }
            wpart[ln] = ip - p;                       // exclusive warp base
        }
        __syncthreads();
        if (t < NUM) sptr[t] = wpart[wd] + inc - v;  // exclusive scan
        if (t == 0)  sptr[NUM] = E;
    }
    __syncthreads();

    for (int ck = wd; ck < 128; ck += 32){
        int e   = ck * 32 + ln;
        int col = cs[e];
        unsigned mask = __match_any_sync(0xffffffffu, col);
        int rank = __popc(mask & ((1u << ln) - 1u));
        if (col >= 0){
            int r   = rs[e];
            int pos = sptr[col] + (int)cnt[ck * NUM + col] + rank;
            g_csr[pos] = make_int2(r, __float_as_int(dinv[col] * dinv[r]));
        }
    }
    if (t <= NUM) g_ptr[t] = sptr[t];
}

// ------------------------- fused GCN mega-kernel (one CTA per batch) ----------
// smem layout (bytes):
//   region0: z[512x264]=135168 -> A_hi[512x144]@0 + A_lo @73728 -> h2[512x264]
//   meta [4096] int2  @ 147456 (32768)   {r, coef}
//   sptr [513]  i32   @ 180224 ( 2052)
//   t3   [512]  f32   @ 184328 ( 2048)
//   Bpack[64x320]     @ 186384 (20480)
#define SM_A_HI  0
#define SM_A_LO  73728
#define SM_META  147456
#define SM_PTR   180224
#define SM_T3    184328
#define SM_BP    186384
#define SM_TOTAL 206864

static __device__ __forceinline__ uint32_t smem_u32(const void* p){
    uint32_t a;
    asm("{ .reg .u64 t; cvta.to.shared.u64 t, %1; cvt.u32.u64 %0, t; }"
        : "=r"(a) : "l"(p));
    return a;
}

__global__ void __launch_bounds__(THREADS, 1)
gcn_mega(const float* __restrict__ x,
         const float* __restrict__ b1,
         const float* __restrict__ b2,
         const float* __restrict__ W3,
         const float* __restrict__ b3,
         float* __restrict__ out)
{
    extern __shared__ char smraw[];
    int2*  meta = (int2*)(smraw + SM_META);
    int*   sptr = (int*)(smraw + SM_PTR);
    float* t3   = (float*)(smraw + SM_T3);

    const uint32_t sbase = smem_u32(smraw);
    const int t  = threadIdx.x;
    const int b  = blockIdx.x;
    const int ln = t & 31;               // lane
    const int gw = t >> 5;               // warp id 0..31

    // ---- async-stage meta + packed B; z-build overlapped -------------------------
    {
#pragma unroll
        for (int i = t; i < EMAX / 2; i += THREADS)           // meta 16B chunks
            cpa16(sbase + SM_META + 16 * i, (const char*)g_csr + 16 * i);
#pragma unroll
        for (int i = t; i < (DH * BSTR) / 16; i += THREADS)   // Bpack 16B chunks
            cpa16(sbase + SM_BP + 16 * i, g_Bpack + 16 * i);
        asm volatile("cp.async.commit_group;");
        if (t <= NUM) sptr[t] = g_ptr[t];

        // z = diag(x) * EW1 (x is a per-warp broadcast LDG; no xs staging)
        const float2* ew2 = (const float2*)g_EW1;
#pragma unroll
        for (int k = 0; k < (NUM * 32) / THREADS; k++){
            int i = t + k * THREADS;            // n*32 + jp
            int n = i >> 5, jp = i & 31;
            float xv = __ldg(x + b * NUM + n);  // all lanes same n -> broadcast
            float2 w = ew2[i];
            *(float2*)(smraw + n * ZSTR + 8 * jp) = make_float2(xv * w.x, xv * w.y);
        }
        asm volatile("cp.async.wait_group 0;");
    }
    __syncthreads();

    // ---- layer 1 agg into registers: warp gw owns CONTIGUOUS nodes 16gw..16gw+15 -
    float2 h1[16];
    {
        float b1x = b1[2 * ln], b1y = b1[2 * ln + 1];
#pragma unroll
        for (int m = 0; m < 16; m++){
            int n = 16 * gw + m;
            int e0 = sptr[n], e1 = sptr[n + 1];
            float a0 = 0.f, a1 = 0.f;
#pragma unroll 4
            for (int e = e0; e < e1; e++){
                int2  rc = meta[e];                        // LDS.64 broadcast
                float c  = __int_as_float(rc.y);
                float2 zv = *(const float2*)(smraw + rc.x * ZSTR + 8 * ln);
                a0 += c * zv.x;
                a1 += c * zv.y;
            }
            h1[m] = make_float2(fmaxf(a0 + b1x, 0.f), fmaxf(a1 + b1y, 0.f));
        }
    }
    __syncthreads();                      // all z reads complete (z dead)

    // ---- write h1 as bf16 hi/lo A tiles (own rows; same-warp ldmatrix follows) ---
#pragma unroll
    for (int m = 0; m < 16; m++){
        int n = 16 * gw + m;
        float2 v = h1[m];
        __nv_bfloat162 hi2 = __float22bfloat162_rn(v);
        float2 r = make_float2(v.x - __bfloat162float(hi2.x),
                               v.y - __bfloat162float(hi2.y));
        __nv_bfloat162 lo2 = __float22bfloat162_rn(r);
        *(__nv_bfloat162*)(smraw + SM_A_HI + n * ASTR + 4 * ln) = hi2;
        *(__nv_bfloat162*)(smraw + SM_A_LO + n * ASTR + 4 * ln) = lo2;
    }
    __syncwarp();                         // warp-local: rows 16gw..16gw+15 only

    // ---- load A fragments (warp w: rows 16w..16w+15, k 0..63, hi+lo) ------------
    uint32_t ah[16], al[16];
    {
        uint32_t abase = sbase + (16 * gw + (ln & 15)) * ASTR + ((ln >> 4) << 4);
#pragma unroll
        for (int kt = 0; kt < 4; kt++) ldm4(&ah[4 * kt], abase + SM_A_HI + 32 * kt);
#pragma unroll
        for (int kt = 0; kt < 4; kt++) ldm4(&al[4 * kt], abase + SM_A_LO + 32 * kt);
    }
    __syncthreads();                      // all A reads done; region reusable as h2

    // ---- h2 = h1 @ W2: 8 n-tiles x 4 k-tiles x 3 passes of mma.m16n8k16 ---------
    {
        const int rowa = 16 * gw + (ln >> 2);
#pragma unroll 1
        for (int nt = 0; nt < 8; nt++){
            float c0 = 0.f, c1 = 0.f, c2 = 0.f, c3 = 0.f;
            const char* bp = smraw + SM_BP + (8 * nt + (ln >> 2)) * BSTR + (ln & 3) * 16;
#pragma unroll
            for (int kt = 0; kt < 4; kt++){
                uint4 v = *(const uint4*)(bp + kt * 64);   // {b0h,b1h,b0l,b1l}
                mma_bf16(c0, c1, c2, c3, &ah[4 * kt], v.x, v.y);
                mma_bf16(c0, c1, c2, c3, &ah[4 * kt], v.z, v.w);
                mma_bf16(c0, c1, c2, c3, &al[4 * kt], v.x, v.y);
            }
            *(float2*)(smraw + rowa * ZSTR + 32 * nt + 8 * (ln & 3)) = make_float2(c0, c1);
            *(float2*)(smraw + (rowa + 8) * ZSTR + 32 * nt + 8 * (ln & 3)) = make_float2(c2, c3);
        }
    }
    __syncthreads();

    // ---- layer 2 agg + relu + W3 dot (dynamic node loop — R8 form) --------------
    {
        float b2x = b2[2 * ln], b2y = b2[2 * ln + 1];
        float w3x = W3[2 * ln], w3y = W3[2 * ln + 1];
        for (int n = gw; n < NUM; n += 32){
            int e0 = sptr[n], e1 = sptr[n + 1];
            float a0 = 0.f, a1 = 0.f;
#pragma unroll 4
            for (int e = e0; e < e1; e++){
                int2  rc = meta[e];
                float c  = __int_as_float(rc.y);
                float2 hv = *(const float2*)(smraw + rc.x * ZSTR + 8 * ln);
                a0 += c * hv.x;
                a1 += c * hv.y;
            }
            a0 = fmaxf(a0 + b2x, 0.f);
            a1 = fmaxf(a1 + b2y, 0.f);
            float v = a0 * w3x + a1 * w3y;
#pragma unroll
            for (int o = 16; o > 0; o >>= 1) v += __shfl_xor_sync(0xffffffffu, v, o);
            if (ln == 0) t3[n] = v;
        }
    }
    __syncthreads();

    // ---- layer 3 logits (register-resident) + softmax/sigmoid --------------------
    if (t < NUM){
        float a = b3[0];
        int e0 = sptr[t], e1 = sptr[t + 1];
#pragma unroll 4
        for (int e = e0; e < e1; e++){
            int2 rc = meta[e];
            a += __int_as_float(rc.y) * t3[rc.x];
        }
        if (t < 32){
            float xv = (t < MAIN_N) ? a : -INFINITY;
            float m = xv;
#pragma unroll
            for (int o = 16; o > 0; o >>= 1) m = fmaxf(m, __shfl_xor_sync(0xffffffffu, m, o));
            float p = (t < MAIN_N) ? expf(xv - m) : 0.f;
            float s = p;
#pragma unroll
            for (int o = 16; o > 0; o >>= 1) s += __shfl_xor_sync(0xffffffffu, s, o);
            if (t < MAIN_N) out[b * NUM + t] = p / s;
        }
        if (t >= MAIN_N) out[b * NUM + t] = 1.f / (1.f + expf(-a));
    }
}

// ------------------------- launcher ------------------------------------------
extern "C" void kernel_launch(void* const* d_in, const int* in_sizes, int n_in,
                              void* d_out, int out_size)
{
    const float* x    = (const float*)d_in[0];
    const float* emb  = (const float*)d_in[1];
    const float* W1   = (const float*)d_in[2];
    const float* b1   = (const float*)d_in[3];
    const float* W2   = (const float*)d_in[4];
    const float* b2   = (const float*)d_in[5];
    const float* W3   = (const float*)d_in[6];
    const float* b3   = (const float*)d_in[7];
    const int*  erow  = (const int*)d_in[8];
    const int*  ecol  = (const int*)d_in[9];
    float* out = (float*)d_out;

    const int E = in_sizes[8];
    const int B = in_sizes[0] / NUM;

    cudaFuncSetAttribute(gcn_mega, cudaFuncAttributeMaxDynamicSharedMemorySize, SM_TOTAL);
    cudaFuncSetAttribute(prep_all, cudaFuncAttributeMaxDynamicSharedMemorySize, PS_TOTAL);

    prep_all<<<34, 1024, PS_TOTAL>>>(emb, W1, W2, erow, ecol, E);
    gcn_mega<<<B, THREADS, SM_TOTAL>>>(x, b1, b2, W3, b3, out);

    (void)n_in; (void)out_size;
}

// round 16
// speedup vs baseline: 1.0603x; 1.0085x over previous
#include <cuda_runtime.h>
#include <cuda_bf16.h>
#include <math.h>
#include <stdint.h>

#define NUM      512
#define DH       64
#define EMAX     4096
#define MAIN_N   10
#define THREADS  1024
#define ZSTR     264           // z / h2 row stride bytes
#define ASTR     144           // A tile row stride bytes (36 words: conflict-free)
#define BSTR     320           // packed B row stride bytes (80 words: LDS.128 conflict-free)

// ------------------------- device scratch (no allocs allowed) ----------------
__device__ __align__(16) int2 g_csr[EMAX];  // {row, coef bits} col-sorted, stable
__device__ int       g_ptr[NUM + 1];
__device__ float     g_EW1[NUM * DH];
__device__ __align__(16) unsigned char g_Bpack[DH * BSTR];  // W2^T hi/lo interleaved

// ------------------------- mma / cp.async / PDL helpers ----------------------
static __device__ __forceinline__ void ldm4(uint32_t* r, uint32_t addr){
    asm volatile("ldmatrix.sync.aligned.m8n8.x4.shared.b16 {%0,%1,%2,%3}, [%4];"
                 : "=r"(r[0]), "=r"(r[1]), "=r"(r[2]), "=r"(r[3]) : "r"(addr));
}
static __device__ __forceinline__ void mma_bf16(float& c0, float& c1, float& c2, float& c3,
                                                const uint32_t* a, uint32_t b0, uint32_t b1){
    asm volatile("mma.sync.aligned.m16n8k16.row.col.f32.bf16.bf16.f32 "
                 "{%0,%1,%2,%3}, {%4,%5,%6,%7}, {%8,%9}, {%0,%1,%2,%3};"
                 : "+f"(c0), "+f"(c1), "+f"(c2), "+f"(c3)
                 : "r"(a[0]), "r"(a[1]), "r"(a[2]), "r"(a[3]), "r"(b0), "r"(b1));
}
static __device__ __forceinline__ void cpa16(uint32_t dst, const void* src){
    asm volatile("cp.async.cg.shared.global [%0], [%1], 16;" :: "r"(dst), "l"(src));
}
static __device__ __forceinline__ void pdl_trigger(){
    asm volatile("griddepcontrol.launch_dependents;" ::: "memory");
}
static __device__ __forceinline__ void pdl_wait(){
    asm volatile("griddepcontrol.wait;" ::: "memory");
}

// ------------------------- unified prep: EW1 / W2-pack / graph ---------------
#define PS_CS    0
#define PS_RS    16384
#define PS_CNT   32768
#define PS_DEG   163840
#define PS_DINV  165888
#define PS_SPTR  167936
#define PS_WP    169992
#define PS_TOTAL 170128

__global__ void __launch_bounds__(1024)
prep_all(const float* __restrict__ emb, const float* __restrict__ W1,
         const float* __restrict__ W2,
         const int* __restrict__ erow, const int* __restrict__ ecol, int E)
{
    const int blk = blockIdx.x;
    if (blk < 32){
        int i = blk * 1024 + threadIdx.x;            // n*64 + d
        int n = i >> 6, d = i & 63;
        float acc = 0.f;
#pragma unroll
        for (int k = 0; k < DH; k++) acc += emb[n * DH + k] * W1[k * DH + d];
        g_EW1[i] = acc;
        pdl_trigger();
        return;
    }
    if (blk == 32){
        // interleaved pack: row n (output col), group g = kt*4+q holds
        // {hi(kp0), hi(kp0+4), lo(kp0), lo(kp0+4)} for k-pair kp0 = 8kt+q
        for (int idx = threadIdx.x; idx < DH * 16; idx += 1024){
            int n = idx >> 4, g = idx & 15;
            int kt = g >> 2, q = g & 3;
            int kp0 = 8 * kt + q, kp1 = kp0 + 4;
            float w00 = W2[(2 * kp0) * DH + n], w01 = W2[(2 * kp0 + 1) * DH + n];
            float w10 = W2[(2 * kp1) * DH + n], w11 = W2[(2 * kp1 + 1) * DH + n];
            __nv_bfloat162 h0 = __float22bfloat162_rn(make_float2(w00, w01));
            __nv_bfloat162 h1 = __float22bfloat162_rn(make_float2(w10, w11));
            __nv_bfloat162 l0 = __float22bfloat162_rn(
                make_float2(w00 - __bfloat162float(h0.x), w01 - __bfloat162float(h0.y)));
            __nv_bfloat162 l1 = __float22bfloat162_rn(
                make_float2(w10 - __bfloat162float(h1.x), w11 - __bfloat162float(h1.y)));
            uint4 v;
            v.x = *(uint32_t*)&h0; v.y = *(uint32_t*)&h1;
            v.z = *(uint32_t*)&l0; v.w = *(uint32_t*)&l1;
            *(uint4*)(g_Bpack + n * BSTR + g * 16) = v;
        }
        pdl_trigger();
        return;
    }

    // ---- graph -> stable col-sorted CSR -----------------------------------------
    extern __shared__ char psm[];
    int*            cs   = (int*)(psm + PS_CS);
    int*            rs   = (int*)(psm + PS_RS);
    unsigned short* cnt  = (unsigned short*)(psm + PS_CNT);
    int*            deg  = (int*)(psm + PS_DEG);
    float*          dinv = (float*)(psm + PS_DINV);
    int*            sptr = (int*)(psm + PS_SPTR);
    int*            wpart= (int*)(psm + PS_WP);

    const int t  = threadIdx.x;
    const int wd = t >> 5;
    const int ln = t & 31;

    for (int e = t; e < EMAX; e += 1024){
        cs[e] = (e < E) ? ecol[e] : -1;
        rs[e] = (e < E) ? erow[e] : 0;
        g_csr[e] = make_int2(0, 0);                  // pads stay coef=0
    }
    for (int i = t; i < (128 * NUM) / 2; i += 1024)
        ((unsigned*)cnt)[i] = 0;
    __syncthreads();

    for (int ck = wd; ck < 128; ck += 32){
        int col = cs[ck * 32 + ln];
        unsigned mask = __match_any_sync(0xffffffffu, col);
        if (col >= 0 && ln == (__ffs(mask) - 1))
            cnt[ck * NUM + col] = (unsigned short)__popc(mask);
    }
    __syncthreads();

    if (t < NUM){
        int run = 0;
#pragma unroll 4
        for (int k = 0; k < 128; k++){
            int v = cnt[k * NUM + t];
            cnt[k * NUM + t] = (unsigned short)run;
            run += v;
        }
        deg[t]  = run;
        dinv[t] = run > 0 ? rsqrtf((float)run) : 0.f;
    }
    __syncthreads();

    // ---- parallel exclusive scan: sptr[t] = sum of deg[0..t) ----------------------
    {
        int v = (t < NUM) ? deg[t] : 0;
        int inc = v;
#pragma unroll
        for (int o = 1; o < 32; o <<= 1){
            int u = __shfl_up_sync(0xffffffffu, inc, o);
            if (ln >= o) inc += u;
        }
        if (ln == 31) wpart[wd] = inc;               // inclusive warp total (wd 0..31)
        __syncthreads();
        if (wd == 0){
            int p = wpart[ln];
            int ip = p;
#pragma unroll
            for (int o = 1; o < 32; o <<= 1){
                int u = __shfl_up_sync(0xffffffffu, ip, o);
                if (ln >= o) ip += u;
            }
            wpart[ln] = ip - p;                       // exclusive warp base
        }
        __syncthreads();
        if (t < NUM) sptr[t] = wpart[wd] + inc - v;  // exclusive scan
        if (t == 0)  sptr[NUM] = E;
    }
    __syncthreads();

    for (int ck = wd; ck < 128; ck += 32){
        int e   = ck * 32 + ln;
        int col = cs[e];
        unsigned mask = __match_any_sync(0xffffffffu, col);
        int rank = __popc(mask & ((1u << ln) - 1u));
        if (col >= 0){
            int r   = rs[e];
            int pos = sptr[col] + (int)cnt[ck * NUM + col] + rank;
            g_csr[pos] = make_int2(r, __float_as_int(dinv[col] * dinv[r]));
        }
    }
    if (t <= NUM) g_ptr[t] = sptr[t];
    pdl_trigger();
}

// ------------------------- fused GCN mega-kernel (one CTA per batch) ----------
// smem layout (bytes):
//   region0: z[512x264]=135168 -> A_hi[512x144]@0 + A_lo @73728 -> h2[512x264]
//   meta [4096] int2  @ 147456 (32768)   {r, coef}
//   sptr [513]  i32   @ 180224 ( 2052)
//   t3   [512]  f32   @ 184328 ( 2048)
//   Bpack[64x320]     @ 186384 (20480)
#define SM_A_HI  0
#define SM_A_LO  73728
#define SM_META  147456
#define SM_PTR   180224
#define SM_T3    184328
#define SM_BP    186384
#define SM_TOTAL 206864

static __device__ __forceinline__ uint32_t smem_u32(const void* p){
    uint32_t a;
    asm("{ .reg .u64 t; cvta.to.shared.u64 t, %1; cvt.u32.u64 %0, t; }"
        : "=r"(a) : "l"(p));
    return a;
}

__global__ void __launch_bounds__(THREADS, 1)
gcn_mega(const float* __restrict__ x,
         const float* __restrict__ b1,
         const float* __restrict__ b2,
         const float* __restrict__ W3,
         const float* __restrict__ b3,
         float* __restrict__ out)
{
    extern __shared__ char smraw[];
    int2*  meta = (int2*)(smraw + SM_META);
    int*   sptr = (int*)(smraw + SM_PTR);
    float* t3   = (float*)(smraw + SM_T3);

    const uint32_t sbase = smem_u32(smraw);
    const int t  = threadIdx.x;
    const int b  = blockIdx.x;
    const int ln = t & 31;               // lane
    const int gw = t >> 5;               // warp id 0..31

    pdl_wait();                          // prep outputs visible past this point

    // ---- async-stage meta + packed B; z-build overlapped -------------------------
    {
#pragma unroll
        for (int i = t; i < EMAX / 2; i += THREADS)           // meta 16B chunks
            cpa16(sbase + SM_META + 16 * i, (const char*)g_csr + 16 * i);
#pragma unroll
        for (int i = t; i < (DH * BSTR) / 16; i += THREADS)   // Bpack 16B chunks
            cpa16(sbase + SM_BP + 16 * i, g_Bpack + 16 * i);
        asm volatile("cp.async.commit_group;");
        if (t <= NUM) sptr[t] = g_ptr[t];

        // z = diag(x) * EW1 (x is a per-warp broadcast LDG; no xs staging)
        const float2* ew2 = (const float2*)g_EW1;
#pragma unroll
        for (int k = 0; k < (NUM * 32) / THREADS; k++){
            int i = t + k * THREADS;            // n*32 + jp
            int n = i >> 5, jp = i & 31;
            float xv = __ldg(x + b * NUM + n);  // all lanes same n -> broadcast
            float2 w = ew2[i];
            *(float2*)(smraw + n * ZSTR + 8 * jp) = make_float2(xv * w.x, xv * w.y);
        }
        asm volatile("cp.async.wait_group 0;");
    }
    __syncthreads();

    // ---- layer 1 agg into registers: warp gw owns CONTIGUOUS nodes 16gw..16gw+15 -
    float2 h1[16];
    {
        float b1x = b1[2 * ln], b1y = b1[2 * ln + 1];
#pragma unroll
        for (int m = 0; m < 16; m++){
            int n = 16 * gw + m;
            int e0 = sptr[n], e1 = sptr[n + 1];
            float a0 = 0.f, a1 = 0.f;
#pragma unroll 4
            for (int e = e0; e < e1; e++){
                int2  rc = meta[e];                        // LDS.64 broadcast
                float c  = __int_as_float(rc.y);
                float2 zv = *(const float2*)(smraw + rc.x * ZSTR + 8 * ln);
                a0 += c * zv.x;
                a1 += c * zv.y;
            }
            h1[m] = make_float2(fmaxf(a0 + b1x, 0.f), fmaxf(a1 + b1y, 0.f));
        }
    }
    __syncthreads();                      // all z reads complete (z dead)

    // ---- write h1 as bf16 hi/lo A tiles (own rows; same-warp ldmatrix follows) ---
#pragma unroll
    for (int m = 0; m < 16; m++){
        int n = 16 * gw + m;
        float2 v = h1[m];
        __nv_bfloat162 hi2 = __float22bfloat162_rn(v);
        float2 r = make_float2(v.x - __bfloat162float(hi2.x),
                               v.y - __bfloat162float(hi2.y));
        __nv_bfloat162 lo2 = __float22bfloat162_rn(r);
        *(__nv_bfloat162*)(smraw + SM_A_HI + n * ASTR + 4 * ln) = hi2;
        *(__nv_bfloat162*)(smraw + SM_A_LO + n * ASTR + 4 * ln) = lo2;
    }
    __syncwarp();                         // warp-local: rows 16gw..16gw+15 only

    // ---- load A fragments (warp w: rows 16w..16w+15, k 0..63, hi+lo) ------------
    uint32_t ah[16], al[16];
    {
        uint32_t abase = sbase + (16 * gw + (ln & 15)) * ASTR + ((ln >> 4) << 4);
#pragma unroll
        for (int kt = 0; kt < 4; kt++) ldm4(&ah[4 * kt], abase + SM_A_HI + 32 * kt);
#pragma unroll
        for (int kt = 0; kt < 4; kt++) ldm4(&al[4 * kt], abase + SM_A_LO + 32 * kt);
    }
    __syncthreads();                      // all A reads done; region reusable as h2

    // ---- h2 = h1 @ W2: 8 n-tiles x 4 k-tiles x 3 passes of mma.m16n8k16 ---------
    {
        const int rowa = 16 * gw + (ln >> 2);
#pragma unroll 1
        for (int nt = 0; nt < 8; nt++){
            float c0 = 0.f, c1 = 0.f, c2 = 0.f, c3 = 0.f;
            const char* bp = smraw + SM_BP + (8 * nt + (ln >> 2)) * BSTR + (ln & 3) * 16;
#pragma unroll
            for (int kt = 0; kt < 4; kt++){
                uint4 v = *(const uint4*)(bp + kt * 64);   // {b0h,b1h,b0l,b1l}
                mma_bf16(c0, c1, c2, c3, &ah[4 * kt], v.x, v.y);
                mma_bf16(c0, c1, c2, c3, &ah[4 * kt], v.z, v.w);
                mma_bf16(c0, c1, c2, c3, &al[4 * kt], v.x, v.y);
            }
            *(float2*)(smraw + rowa * ZSTR + 32 * nt + 8 * (ln & 3)) = make_float2(c0, c1);
            *(float2*)(smraw + (rowa + 8) * ZSTR + 32 * nt + 8 * (ln & 3)) = make_float2(c2, c3);
        }
    }
    __syncthreads();

    // ---- layer 2 agg + relu + W3 dot (dynamic node loop — R8 form) --------------
    {
        float b2x = b2[2 * ln], b2y = b2[2 * ln + 1];
        float w3x = W3[2 * ln], w3y = W3[2 * ln + 1];
        for (int n = gw; n < NUM; n += 32){
            int e0 = sptr[n], e1 = sptr[n + 1];
            float a0 = 0.f, a1 = 0.f;
#pragma unroll 4
            for (int e = e0; e < e1; e++){
                int2  rc = meta[e];
                float c  = __int_as_float(rc.y);
                float2 hv = *(const float2*)(smraw + rc.x * ZSTR + 8 * ln);
                a0 += c * hv.x;
                a1 += c * hv.y;
            }
            a0 = fmaxf(a0 + b2x, 0.f);
            a1 = fmaxf(a1 + b2y, 0.f);
            float v = a0 * w3x + a1 * w3y;
#pragma unroll
            for (int o = 16; o > 0; o >>= 1) v += __shfl_xor_sync(0xffffffffu, v, o);
            if (ln == 0) t3[n] = v;
        }
    }
    __syncthreads();

    // ---- layer 3 logits (register-resident) + softmax/sigmoid --------------------
    if (t < NUM){
        float a = b3[0];
        int e0 = sptr[t], e1 = sptr[t + 1];
#pragma unroll 4
        for (int e = e0; e < e1; e++){
            int2 rc = meta[e];
            a += __int_as_float(rc.y) * t3[rc.x];
        }
        if (t < 32){
            float xv = (t < MAIN_N) ? a : -INFINITY;
            float m = xv;
#pragma unroll
            for (int o = 16; o > 0; o >>= 1) m = fmaxf(m, __shfl_xor_sync(0xffffffffu, m, o));
            float p = (t < MAIN_N) ? expf(xv - m) : 0.f;
            float s = p;
#pragma unroll
            for (int o = 16; o > 0; o >>= 1) s += __shfl_xor_sync(0xffffffffu, s, o);
            if (t < MAIN_N) out[b * NUM + t] = p / s;
        }
        if (t >= MAIN_N) out[b * NUM + t] = 1.f / (1.f + expf(-a));
    }
}

// ------------------------- launcher ------------------------------------------
extern "C" void kernel_launch(void* const* d_in, const int* in_sizes, int n_in,
                              void* d_out, int out_size)
{
    const float* x    = (const float*)d_in[0];
    const float* emb  = (const float*)d_in[1];
    const float* W1   = (const float*)d_in[2];
    const float* b1   = (const float*)d_in[3];
    const float* W2   = (const float*)d_in[4];
    const float* b2   = (const float*)d_in[5];
    const float* W3   = (const float*)d_in[6];
    const float* b3   = (const float*)d_in[7];
    const int*  erow  = (const int*)d_in[8];
    const int*  ecol  = (const int*)d_in[9];
    float* out = (float*)d_out;

    const int E = in_sizes[8];
    const int B = in_sizes[0] / NUM;

    cudaFuncSetAttribute(gcn_mega, cudaFuncAttributeMaxDynamicSharedMemorySize, SM_TOTAL);
    cudaFuncSetAttribute(prep_all, cudaFuncAttributeMaxDynamicSharedMemorySize, PS_TOTAL);

    prep_all<<<34, 1024, PS_TOTAL>>>(emb, W1, W2, erow, ecol, E);

    // mega launched with programmatic dependent launch: overlaps prep's tail.
    cudaLaunchConfig_t cfg = {};
    cfg.gridDim = dim3((unsigned)B);
    cfg.blockDim = dim3(THREADS);
    cfg.dynamicSmemBytes = SM_TOTAL;
    cfg.stream = 0;
    cudaLaunchAttribute attr[1];
    attr[0].id = cudaLaunchAttributeProgrammaticStreamSerialization;
    attr[0].val.programmaticStreamSerializationAllowed = 1;
    cfg.attrs = attr;
    cfg.numAttrs = 1;
    cudaLaunchKernelEx(&cfg, gcn_mega, x, b1, b2, W3, b3, out);

    (void)n_in; (void)out_size;
}